// round 15
// baseline (speedup 1.0000x reference)
#include <cuda_runtime.h>
#include <cuda_bf16.h>
#include <cuda_fp16.h>
#include <cstdint>

#define D_MODEL 256
#define N_NODES 20
#define N_HEADS 8
#define BMAX    8192
#define MMAX    (BMAX * N_NODES)   // 163840 rows

// ---------------- scratch (device globals: allocation-free) ----------------
__device__ __half g_xh[(size_t)MMAX * 256];     // x as fp16
__device__ __half g_wh[768 * 768];              // conv weights fp16 [o][j=t*256+i]
__device__ __half g_woh[256 * 256];             // wo fp16 [o][i]
__device__ __half g_qkvh[(size_t)MMAX * 768];   // q|k|v after LN+residual (fp16)
__device__ __half g_ah[(size_t)MMAX * 256];     // attn out fp16
__device__ float  g_bias[N_HEADS * 20 * 20];    // rel + alpha*gbias combined

// ---------------- warp-MMA helpers (baseline PTX: sm_80+) ----------------
__device__ __forceinline__ uint32_t smem_u32(const void* p) {
    uint32_t a;
    asm("{ .reg .u64 t; cvta.to.shared.u64 t, %1; cvt.u32.u64 %0, t; }"
        : "=r"(a) : "l"(p));
    return a;
}
__device__ __forceinline__ void ldsm4(uint32_t& r0, uint32_t& r1,
                                      uint32_t& r2, uint32_t& r3, uint32_t addr) {
    asm volatile("ldmatrix.sync.aligned.m8n8.x4.shared.b16 {%0,%1,%2,%3}, [%4];"
                 : "=r"(r0), "=r"(r1), "=r"(r2), "=r"(r3) : "r"(addr));
}
__device__ __forceinline__ void ldsm4t(uint32_t& r0, uint32_t& r1,
                                       uint32_t& r2, uint32_t& r3, uint32_t addr) {
    asm volatile("ldmatrix.sync.aligned.m8n8.x4.trans.shared.b16 {%0,%1,%2,%3}, [%4];"
                 : "=r"(r0), "=r"(r1), "=r"(r2), "=r"(r3) : "r"(addr));
}
__device__ __forceinline__ void mma_f16(float* d,
                                        const uint32_t* a,
                                        uint32_t b0, uint32_t b1) {
    asm volatile(
        "mma.sync.aligned.m16n8k16.row.col.f32.f16.f16.f32 "
        "{%0,%1,%2,%3}, {%4,%5,%6,%7}, {%8,%9}, {%0,%1,%2,%3};"
        : "+f"(d[0]), "+f"(d[1]), "+f"(d[2]), "+f"(d[3])
        : "r"(a[0]), "r"(a[1]), "r"(a[2]), "r"(a[3]), "r"(b0), "r"(b1));
}
__device__ __forceinline__ uint32_t pack_h2(float x, float y) {
    __half2 h = __floats2half2_rn(x, y);
    return *reinterpret_cast<uint32_t*>(&h);
}
__device__ __forceinline__ uint32_t swz128(uint32_t r, uint32_t kq) {
    return r * 128 + ((kq ^ (r & 7)) * 16);
}
__device__ __forceinline__ void cp16(uint32_t dst, const void* src, int srcsz) {
    asm volatile("cp.async.cg.shared.global [%0], [%1], 16, %2;"
                 :: "r"(dst), "l"(__cvta_generic_to_global(src)), "r"(srcsz)
                 : "memory");
}
__device__ __forceinline__ void cp16_ca(uint32_t dst, const void* src) {
    asm volatile("cp.async.ca.shared.global [%0], [%1], 16;"
                 :: "r"(dst), "l"(__cvta_generic_to_global(src))
                 : "memory");
}
__device__ __forceinline__ void cp_commit() {
    asm volatile("cp.async.commit_group;" ::: "memory");
}
template<int N>
__device__ __forceinline__ void cp_wait() {
    asm volatile("cp.async.wait_group %0;" :: "n"(N) : "memory");
}

// ---------------- merged prep kernel ----------------
__global__ void prep_all(const float* __restrict__ x,
                         const float* __restrict__ wq, const float* __restrict__ wk,
                         const float* __restrict__ wv, const float* __restrict__ wo,
                         const float* __restrict__ rel, const float* __restrict__ gbias,
                         const float* __restrict__ alphap, int total4) {
    int i = blockIdx.x * blockDim.x + threadIdx.x;
    if (i < total4) {
        float4 v = reinterpret_cast<const float4*>(x)[i];
        __half2 h0, h1;
        h0.x = __float2half(v.x); h0.y = __float2half(v.y);
        h1.x = __float2half(v.z); h1.y = __float2half(v.w);
        reinterpret_cast<__half2*>(g_xh)[i * 2]     = h0;
        reinterpret_cast<__half2*>(g_xh)[i * 2 + 1] = h1;
    }
    if (i < 768 * 768) {
        int o = i / 768, j = i % 768;
        int t = j >> 8, d = j & 255;
        const float* w = (o < 256) ? wq : (o < 512) ? wk : wv;
        int oc = o & 255;
        g_wh[i] = __float2half(w[(oc * 256 + d) * 3 + t]);
    }
    if (i < 256 * 256) {
        g_woh[i] = __float2half(wo[i]);
    }
    if (i < N_HEADS * 400) {
        int h = i / 400, rc = i % 400;
        int r = rc / 20, c = rc % 20;
        g_bias[i] = rel[(r - c + 19) * 8 + h] + alphap[0] * gbias[i];
    }
}

// ---------------- fused conv GEMM + LayerNorm + residual ----------------
// Per block: 64 rows x 256 cols (one q/k/v segment). BK=64, 2-stage cp.async,
// single barrier per chunk, 2 CTAs/SM. Hoisted load addressing.
#define CSTAGE 40960
#define SMEM_CONV (2 * CSTAGE + 1024 + 2048)

__global__ __launch_bounds__(256, 2)
void conv_ln_kernel(const float* __restrict__ x,
                    const float* __restrict__ gq, const float* __restrict__ bq,
                    const float* __restrict__ gk, const float* __restrict__ bk,
                    const float* __restrict__ gv, const float* __restrict__ bv) {
    extern __shared__ __align__(16) char smem[];
    const uint32_t sb = smem_u32(smem);
    float* red = reinterpret_cast<float*>(smem + 2 * CSTAGE);          // [64][2]
    float* gam = reinterpret_cast<float*>(smem + 2 * CSTAGE + 1024);   // [256]
    float* bet = reinterpret_cast<float*>(smem + 2 * CSTAGE + 2048);   // [256]

    int tid = threadIdx.x, lane = tid & 31, wid = tid >> 5;
    int seg = blockIdx.x;              // 0=q 1=k 2=v
    int row0 = blockIdx.y * 64;
    int wm = (wid >> 2) * 32;          // 2 warp-rows of 32
    int wn = (wid & 3) * 64;           // 4 warp-cols of 64

    {
        const float* gsel = (seg == 0) ? gq : (seg == 1) ? gk : gv;
        const float* bsel = (seg == 0) ? bq : (seg == 1) ? bk : bv;
        gam[tid] = gsel[tid];
        bet[tid] = bsel[tid];
        if (tid < 128) red[tid] = 0.f;
    }

    float acc[2][8][4];
#pragma unroll
    for (int i = 0; i < 2; i++)
#pragma unroll
        for (int j = 0; j < 8; j++)
#pragma unroll
            for (int q = 0; q < 4; q++) acc[i][j][q] = 0.f;

    // ---- hoisted per-thread load state ----
    const int rA = tid >> 3, kqA = tid & 7;
    const uint32_t dst0 = swz128((uint32_t)rA, (uint32_t)kqA);   // +it*4096 per slab
    const int m0 = row0 + rA;
    const int m1 = m0 + 32;
    const int n0 = m0 % N_NODES;
    const int n1 = m1 % N_NODES;
    const __half* pB = g_wh + (size_t)(seg * 256 + rA) * 768 + kqA * 8;  // +64/chunk
    const __half* pA0 = g_xh;  const __half* pA1 = g_xh;
    int szA0 = 0, szA1 = 0;

    auto issue = [&](int s, int kt) {
        uint32_t stg = sb + (uint32_t)s * CSTAGE;
        if ((kt & 3) == 0) {             // tap change: div-free recompute
            int t = kt >> 2;
            int s0 = n0 + t - 1, s1 = n1 + t - 1;
            int ok0 = ((unsigned)s0 < (unsigned)N_NODES);
            int ok1 = ((unsigned)s1 < (unsigned)N_NODES);
            pA0 = g_xh + (size_t)(ok0 ? (m0 + t - 1) : m0) * 256 + kqA * 8;
            pA1 = g_xh + (size_t)(ok1 ? (m1 + t - 1) : m1) * 256 + kqA * 8;
            szA0 = ok0 ? 16 : 0;
            szA1 = ok1 ? 16 : 0;
        }
        cp16(stg + dst0,        pA0, szA0);
        cp16(stg + dst0 + 4096, pA1, szA1);
        uint32_t bdst = stg + 8192 + dst0;
#pragma unroll
        for (int it = 0; it < 8; it++)
            cp16_ca(bdst + it * 4096, pB + it * 24576);
        cp_commit();
        pA0 += 64; pA1 += 64; pB += 64;
    };

    const uint32_t offA0 = swz128(wm + (lane & 15), (lane >> 4));
    const uint32_t offA1 = swz128(wm + 16 + (lane & 15), (lane >> 4));
    uint32_t offB[4];
#pragma unroll
    for (int np = 0; np < 4; np++)
        offB[np] = swz128(wn + np * 16 + (lane & 7) + ((lane >> 4) << 3),
                          (lane >> 3) & 1);

    auto compute = [&](int s) {
        uint32_t base = sb + (uint32_t)s * CSTAGE;
#pragma unroll
        for (int ks = 0; ks < 4; ks++) {
            uint32_t kx = (uint32_t)ks * 32;
            uint32_t fA[2][4];
            ldsm4(fA[0][0], fA[0][1], fA[0][2], fA[0][3], base + (offA0 ^ kx));
            ldsm4(fA[1][0], fA[1][1], fA[1][2], fA[1][3], base + (offA1 ^ kx));
#pragma unroll
            for (int np = 0; np < 4; np++) {
                uint32_t ad = base + 8192 + (offB[np] ^ kx);
                uint32_t b0, b1, b2, b3;
                ldsm4(b0, b1, b2, b3, ad);
#pragma unroll
                for (int mf = 0; mf < 2; mf++) {
                    mma_f16(acc[mf][2 * np],     fA[mf], b0, b1);
                    mma_f16(acc[mf][2 * np + 1], fA[mf], b2, b3);
                }
            }
        }
    };

    const int KT = 12;
    issue(0, 0);
#pragma unroll 1
    for (int kt = 0; kt < KT; kt++) {
        cp_wait<0>();
        __syncthreads();
        if (kt + 1 < KT) issue((kt + 1) & 1, kt + 1);
        compute(kt & 1);
    }

    // ---- LN + residual epilogue (fp16 output) ----
#pragma unroll
    for (int mf = 0; mf < 2; mf++) {
#pragma unroll
        for (int rr = 0; rr < 2; rr++) {
            int rloc = wm + mf * 16 + (lane >> 2) + rr * 8;
            float s = 0.f, s2 = 0.f;
#pragma unroll
            for (int nf = 0; nf < 8; nf++) {
                float c0 = acc[mf][nf][rr * 2];
                float c1 = acc[mf][nf][rr * 2 + 1];
                s += c0 + c1; s2 += c0 * c0 + c1 * c1;
            }
            s  += __shfl_xor_sync(0xffffffffu, s, 1);
            s  += __shfl_xor_sync(0xffffffffu, s, 2);
            s2 += __shfl_xor_sync(0xffffffffu, s2, 1);
            s2 += __shfl_xor_sync(0xffffffffu, s2, 2);
            if ((lane & 3) == 0) {
                atomicAdd(&red[rloc * 2], s);
                atomicAdd(&red[rloc * 2 + 1], s2);
            }
        }
    }
    __syncthreads();

#pragma unroll
    for (int mf = 0; mf < 2; mf++) {
#pragma unroll
        for (int rr = 0; rr < 2; rr++) {
            int rloc = wm + mf * 16 + (lane >> 2) + rr * 8;
            int rg = row0 + rloc;
            float mean = red[rloc * 2] * (1.0f / 256.0f);
            float var  = red[rloc * 2 + 1] * (1.0f / 256.0f) - mean * mean;
            float inv  = rsqrtf(var + 1e-5f);
#pragma unroll
            for (int nf = 0; nf < 8; nf++) {
                int cloc = wn + nf * 8 + 2 * (lane & 3);
                float2 xv = *reinterpret_cast<const float2*>(
                    &x[(size_t)rg * 256 + cloc]);
                float c0 = acc[mf][nf][rr * 2];
                float c1 = acc[mf][nf][rr * 2 + 1];
                float o0 = xv.x + (c0 - mean) * inv * gam[cloc]     + bet[cloc];
                float o1 = xv.y + (c1 - mean) * inv * gam[cloc + 1] + bet[cloc + 1];
                *reinterpret_cast<__half2*>(
                    &g_qkvh[(size_t)rg * 768 + seg * 256 + cloc]) =
                    __floats2half2_rn(o0, o1);
            }
        }
    }
}

// ---------------- proj GEMM (single-pass fp16, 64x256, BK=64, 2-stage) ----------------
#define SMEM_PROJ (2 * CSTAGE)

__global__ __launch_bounds__(256, 2)
void proj_gemm(const float* __restrict__ bo, float* __restrict__ outp) {
    extern __shared__ __align__(16) char smem[];
    const uint32_t sb = smem_u32(smem);

    int tid = threadIdx.x, lane = tid & 31, wid = tid >> 5;
    int row0 = blockIdx.x * 64;
    int wm = (wid >> 2) * 32;
    int wn = (wid & 3) * 64;

    float acc[2][8][4];
#pragma unroll
    for (int i = 0; i < 2; i++)
#pragma unroll
        for (int j = 0; j < 8; j++)
#pragma unroll
            for (int q = 0; q < 4; q++) acc[i][j][q] = 0.f;

    const int rA = tid >> 3, kqA = tid & 7;
    const uint32_t dst0 = swz128((uint32_t)rA, (uint32_t)kqA);
    const __half* pA = g_ah + (size_t)(row0 + rA) * 256 + kqA * 8;
    const __half* pB = g_woh + (size_t)rA * 256 + kqA * 8;

    auto issue = [&](int s) {
        uint32_t stg = sb + (uint32_t)s * CSTAGE;
        cp16(stg + dst0,        pA, 16);
        cp16(stg + dst0 + 4096, pA + 8192, 16);
        uint32_t bdst = stg + 8192 + dst0;
#pragma unroll
        for (int it = 0; it < 8; it++)
            cp16_ca(bdst + it * 4096, pB + it * 8192);
        cp_commit();
        pA += 64; pB += 64;
    };

    const uint32_t offA0 = swz128(wm + (lane & 15), (lane >> 4));
    const uint32_t offA1 = swz128(wm + 16 + (lane & 15), (lane >> 4));
    uint32_t offB[4];
#pragma unroll
    for (int np = 0; np < 4; np++)
        offB[np] = swz128(wn + np * 16 + (lane & 7) + ((lane >> 4) << 3),
                          (lane >> 3) & 1);

    auto compute = [&](int s) {
        uint32_t base = sb + (uint32_t)s * CSTAGE;
#pragma unroll
        for (int ks = 0; ks < 4; ks++) {
            uint32_t kx = (uint32_t)ks * 32;
            uint32_t fA[2][4];
            ldsm4(fA[0][0], fA[0][1], fA[0][2], fA[0][3], base + (offA0 ^ kx));
            ldsm4(fA[1][0], fA[1][1], fA[1][2], fA[1][3], base + (offA1 ^ kx));
#pragma unroll
            for (int np = 0; np < 4; np++) {
                uint32_t ad = base + 8192 + (offB[np] ^ kx);
                uint32_t b0, b1, b2, b3;
                ldsm4(b0, b1, b2, b3, ad);
#pragma unroll
                for (int mf = 0; mf < 2; mf++) {
                    mma_f16(acc[mf][2 * np],     fA[mf], b0, b1);
                    mma_f16(acc[mf][2 * np + 1], fA[mf], b2, b3);
                }
            }
        }
    };

    const int KT = 4;
    issue(0);
#pragma unroll 1
    for (int kt = 0; kt < KT; kt++) {
        cp_wait<0>();
        __syncthreads();
        if (kt + 1 < KT) issue((kt + 1) & 1);
        compute(kt & 1);
    }

#pragma unroll
    for (int mf = 0; mf < 2; mf++) {
        int row = row0 + wm + mf * 16 + (lane >> 2);
#pragma unroll
        for (int nf = 0; nf < 8; nf++) {
            int col = wn + nf * 8 + 2 * (lane & 3);
            float* d = acc[mf][nf];
            float b0 = bo[col], b1 = bo[col + 1];
            *reinterpret_cast<float2*>(&outp[(size_t)row * 256 + col]) =
                make_float2(d[0] + b0, d[1] + b1);
            *reinterpret_cast<float2*>(&outp[(size_t)(row + 8) * 256 + col]) =
                make_float2(d[2] + b0, d[3] + b1);
        }
    }
}

// ---------------- attention: HMMA per (b, head), smem bias table ----------------
__global__ __launch_bounds__(128)
void attn_kernel() {
    __shared__ __half q_s[4][32][40];
    __shared__ __half k_s[4][32][40];
    __shared__ __half v_s[4][32][40];
    __shared__ float bias_s[4][400];
    int lane = threadIdx.x & 31;
    int wid  = threadIdx.x >> 5;
    int h = blockIdx.y * 4 + wid;
    int b = blockIdx.x;
    int tid = threadIdx.x;

    {
        const float* src = &g_bias[blockIdx.y * 4 * 400];
        float* dst = &bias_s[0][0];
        for (int i = tid; i < 400; i += 128)
            *reinterpret_cast<float4*>(dst + i * 4) =
                *reinterpret_cast<const float4*>(src + i * 4);
    }

    {
        int r = lane;
        if (r < 20) {
            const __half* basep = &g_qkvh[(size_t)(b * 20 + r) * 768 + h * 32];
#pragma unroll
            for (int c = 0; c < 4; c++) {
                *reinterpret_cast<uint4*>(&q_s[wid][r][c * 8]) =
                    *reinterpret_cast<const uint4*>(basep + c * 8);
                *reinterpret_cast<uint4*>(&k_s[wid][r][c * 8]) =
                    *reinterpret_cast<const uint4*>(basep + 256 + c * 8);
                *reinterpret_cast<uint4*>(&v_s[wid][r][c * 8]) =
                    *reinterpret_cast<const uint4*>(basep + 512 + c * 8);
            }
        } else {
            uint4 z = make_uint4(0, 0, 0, 0);
#pragma unroll
            for (int c = 0; c < 4; c++) {
                *reinterpret_cast<uint4*>(&q_s[wid][r][c * 8]) = z;
                *reinterpret_cast<uint4*>(&k_s[wid][r][c * 8]) = z;
                *reinterpret_cast<uint4*>(&v_s[wid][r][c * 8]) = z;
            }
        }
    }
    __syncthreads();

    const uint32_t sq = smem_u32(&q_s[wid][0][0]);
    const uint32_t sk = smem_u32(&k_s[wid][0][0]);
    const uint32_t sv = smem_u32(&v_s[wid][0][0]);
    int g = lane >> 2, t = lane & 3;

    float c[2][4][4];
#pragma unroll
    for (int i = 0; i < 2; i++)
#pragma unroll
        for (int j = 0; j < 4; j++)
#pragma unroll
            for (int q = 0; q < 4; q++) c[i][j][q] = 0.f;

#pragma unroll
    for (int ks = 0; ks < 2; ks++) {
        uint32_t a[2][4];
#pragma unroll
        for (int mt = 0; mt < 2; mt++) {
            uint32_t ad = sq + (mt * 16 + (lane & 15)) * 80 +
                          (ks * 16 + (lane >> 4) * 8) * 2;
            ldsm4(a[mt][0], a[mt][1], a[mt][2], a[mt][3], ad);
        }
        uint32_t bf[2][4];
#pragma unroll
        for (int np = 0; np < 2; np++) {
            uint32_t ad = sk + (np * 16 + (lane & 7) + ((lane >> 4) << 3)) * 80 +
                          (ks * 2 + ((lane >> 3) & 1)) * 16;
            ldsm4(bf[np][0], bf[np][1], bf[np][2], bf[np][3], ad);
        }
#pragma unroll
        for (int mt = 0; mt < 2; mt++)
#pragma unroll
            for (int nt = 0; nt < 4; nt++)
                mma_f16(c[mt][nt], a[mt],
                        bf[nt >> 1][(nt & 1) * 2], bf[nt >> 1][(nt & 1) * 2 + 1]);
    }

#pragma unroll
    for (int mt = 0; mt < 2; mt++)
#pragma unroll
        for (int nt = 0; nt < 4; nt++)
#pragma unroll
            for (int q = 0; q < 4; q++) {
                int row = mt * 16 + g + (q >> 1) * 8;
                int col = nt * 8 + 2 * t + (q & 1);
                if (row < 20 && col < 20) {
                    c[mt][nt][q] = c[mt][nt][q] * 0.17677669529663689f +
                                   bias_s[wid][row * 20 + col];
                } else {
                    c[mt][nt][q] = -1e30f;
                }
            }

#pragma unroll
    for (int mt = 0; mt < 2; mt++) {
        float m0 = -1e30f, m1 = -1e30f;
#pragma unroll
        for (int nt = 0; nt < 4; nt++) {
            m0 = fmaxf(m0, fmaxf(c[mt][nt][0], c[mt][nt][1]));
            m1 = fmaxf(m1, fmaxf(c[mt][nt][2], c[mt][nt][3]));
        }
        m0 = fmaxf(m0, __shfl_xor_sync(0xffffffffu, m0, 1));
        m0 = fmaxf(m0, __shfl_xor_sync(0xffffffffu, m0, 2));
        m1 = fmaxf(m1, __shfl_xor_sync(0xffffffffu, m1, 1));
        m1 = fmaxf(m1, __shfl_xor_sync(0xffffffffu, m1, 2));
        float s0 = 0.f, s1 = 0.f;
#pragma unroll
        for (int nt = 0; nt < 4; nt++) {
            c[mt][nt][0] = __expf(c[mt][nt][0] - m0);
            c[mt][nt][1] = __expf(c[mt][nt][1] - m0);
            c[mt][nt][2] = __expf(c[mt][nt][2] - m1);
            c[mt][nt][3] = __expf(c[mt][nt][3] - m1);
            s0 += c[mt][nt][0] + c[mt][nt][1];
            s1 += c[mt][nt][2] + c[mt][nt][3];
        }
        s0 += __shfl_xor_sync(0xffffffffu, s0, 1);
        s0 += __shfl_xor_sync(0xffffffffu, s0, 2);
        s1 += __shfl_xor_sync(0xffffffffu, s1, 1);
        s1 += __shfl_xor_sync(0xffffffffu, s1, 2);
        float i0 = 1.f / s0, i1 = 1.f / s1;
#pragma unroll
        for (int nt = 0; nt < 4; nt++) {
            c[mt][nt][0] *= i0; c[mt][nt][1] *= i0;
            c[mt][nt][2] *= i1; c[mt][nt][3] *= i1;
        }
    }

    float o[2][4][4];
#pragma unroll
    for (int i = 0; i < 2; i++)
#pragma unroll
        for (int j = 0; j < 4; j++)
#pragma unroll
            for (int q = 0; q < 4; q++) o[i][j][q] = 0.f;

#pragma unroll
    for (int ks = 0; ks < 2; ks++) {
        uint32_t pa[2][4];
#pragma unroll
        for (int mt = 0; mt < 2; mt++) {
            pa[mt][0] = pack_h2(c[mt][2 * ks][0],     c[mt][2 * ks][1]);
            pa[mt][1] = pack_h2(c[mt][2 * ks][2],     c[mt][2 * ks][3]);
            pa[mt][2] = pack_h2(c[mt][2 * ks + 1][0], c[mt][2 * ks + 1][1]);
            pa[mt][3] = pack_h2(c[mt][2 * ks + 1][2], c[mt][2 * ks + 1][3]);
        }
        uint32_t bv[2][4];
#pragma unroll
        for (int dp = 0; dp < 2; dp++) {
            uint32_t ad = sv + (ks * 16 + (lane & 15)) * 80 +
                          (dp * 16 + ((lane >> 4) << 3)) * 2;
            ldsm4t(bv[dp][0], bv[dp][1], bv[dp][2], bv[dp][3], ad);
        }
#pragma unroll
        for (int mt = 0; mt < 2; mt++)
#pragma unroll
            for (int nt = 0; nt < 4; nt++)
                mma_f16(o[mt][nt], pa[mt],
                        bv[nt >> 1][(nt & 1) * 2], bv[nt >> 1][(nt & 1) * 2 + 1]);
    }

#pragma unroll
    for (int mt = 0; mt < 2; mt++)
#pragma unroll
        for (int q2 = 0; q2 < 2; q2++) {
            int row = mt * 16 + g + q2 * 8;
            if (row < 20) {
                __half* dst = &g_ah[(size_t)(b * 20 + row) * 256 + h * 32];
#pragma unroll
                for (int nt = 0; nt < 4; nt++) {
                    int col = nt * 8 + 2 * t;
                    *reinterpret_cast<__half2*>(dst + col) =
                        __floats2half2_rn(o[mt][nt][q2 * 2], o[mt][nt][q2 * 2 + 1]);
                }
            }
        }
}

// ---------------- launch ----------------
extern "C" void kernel_launch(void* const* d_in, const int* in_sizes, int n_in,
                              void* d_out, int out_size) {
    const float* x     = (const float*)d_in[0];
    const float* wq    = (const float*)d_in[1];
    const float* wk    = (const float*)d_in[2];
    const float* wv    = (const float*)d_in[3];
    const float* gq    = (const float*)d_in[4];
    const float* bq    = (const float*)d_in[5];
    const float* gk    = (const float*)d_in[6];
    const float* bk    = (const float*)d_in[7];
    const float* gv    = (const float*)d_in[8];
    const float* bv    = (const float*)d_in[9];
    const float* rel   = (const float*)d_in[10];
    const float* gbias = (const float*)d_in[11];
    const float* alpha = (const float*)d_in[12];
    const float* wo    = (const float*)d_in[13];
    const float* bo    = (const float*)d_in[14];
    float* out = (float*)d_out;

    int B = in_sizes[0] / (N_NODES * D_MODEL);
    int M = B * N_NODES;

    cudaFuncSetAttribute(conv_ln_kernel,
                         cudaFuncAttributeMaxDynamicSharedMemorySize, SMEM_CONV);
    cudaFuncSetAttribute(proj_gemm,
                         cudaFuncAttributeMaxDynamicSharedMemorySize, SMEM_PROJ);

    int total4 = M * 64;
    prep_all<<<(total4 + 255) / 256, 256>>>(x, wq, wk, wv, wo, rel, gbias,
                                            alpha, total4);

    conv_ln_kernel<<<dim3(3, M / 64), 256, SMEM_CONV>>>(
        x, gq, bq, gk, bk, gv, bv);

    attn_kernel<<<dim3(B, 2), 128>>>();

    proj_gemm<<<M / 64, 256, SMEM_PROJ>>>(bo, out);
}

// round 16
// speedup vs baseline: 1.0383x; 1.0383x over previous
#include <cuda_runtime.h>
#include <cuda_bf16.h>
#include <cuda_fp16.h>
#include <cstdint>

#define D_MODEL 256
#define N_NODES 20
#define N_HEADS 8
#define BMAX    8192
#define MMAX    (BMAX * N_NODES)   // 163840 rows

// ---------------- scratch (device globals: allocation-free) ----------------
__device__ __half g_xh[(size_t)MMAX * 256];     // x as fp16
__device__ __half g_wh[768 * 768];              // conv weights fp16 [o][j=t*256+i]
__device__ __half g_woh[256 * 256];             // wo fp16 [o][i]
__device__ __half g_qkvh[(size_t)MMAX * 768];   // q|k|v after LN+residual (fp16)
__device__ __half g_ah[(size_t)MMAX * 256];     // attn out fp16
__device__ float  g_bias[N_HEADS * 20 * 20];    // rel + alpha*gbias combined

// ---------------- warp-MMA helpers (baseline PTX: sm_80+) ----------------
__device__ __forceinline__ uint32_t smem_u32(const void* p) {
    uint32_t a;
    asm("{ .reg .u64 t; cvta.to.shared.u64 t, %1; cvt.u32.u64 %0, t; }"
        : "=r"(a) : "l"(p));
    return a;
}
__device__ __forceinline__ void ldsm4(uint32_t& r0, uint32_t& r1,
                                      uint32_t& r2, uint32_t& r3, uint32_t addr) {
    asm volatile("ldmatrix.sync.aligned.m8n8.x4.shared.b16 {%0,%1,%2,%3}, [%4];"
                 : "=r"(r0), "=r"(r1), "=r"(r2), "=r"(r3) : "r"(addr));
}
__device__ __forceinline__ void ldsm4t(uint32_t& r0, uint32_t& r1,
                                       uint32_t& r2, uint32_t& r3, uint32_t addr) {
    asm volatile("ldmatrix.sync.aligned.m8n8.x4.trans.shared.b16 {%0,%1,%2,%3}, [%4];"
                 : "=r"(r0), "=r"(r1), "=r"(r2), "=r"(r3) : "r"(addr));
}
__device__ __forceinline__ void mma_f16(float* d,
                                        const uint32_t* a,
                                        uint32_t b0, uint32_t b1) {
    asm volatile(
        "mma.sync.aligned.m16n8k16.row.col.f32.f16.f16.f32 "
        "{%0,%1,%2,%3}, {%4,%5,%6,%7}, {%8,%9}, {%0,%1,%2,%3};"
        : "+f"(d[0]), "+f"(d[1]), "+f"(d[2]), "+f"(d[3])
        : "r"(a[0]), "r"(a[1]), "r"(a[2]), "r"(a[3]), "r"(b0), "r"(b1));
}
__device__ __forceinline__ uint32_t pack_h2(float x, float y) {
    __half2 h = __floats2half2_rn(x, y);
    return *reinterpret_cast<uint32_t*>(&h);
}
__device__ __forceinline__ uint32_t swz128(uint32_t r, uint32_t kq) {
    return r * 128 + ((kq ^ (r & 7)) * 16);
}
__device__ __forceinline__ void cp16(uint32_t dst, const void* src, int srcsz) {
    asm volatile("cp.async.cg.shared.global [%0], [%1], 16, %2;"
                 :: "r"(dst), "l"(__cvta_generic_to_global(src)), "r"(srcsz)
                 : "memory");
}
__device__ __forceinline__ void cp_commit() {
    asm volatile("cp.async.commit_group;" ::: "memory");
}
template<int N>
__device__ __forceinline__ void cp_wait() {
    asm volatile("cp.async.wait_group %0;" :: "n"(N) : "memory");
}

// ---------------- merged prep kernel ----------------
__global__ void prep_all(const float* __restrict__ x,
                         const float* __restrict__ wq, const float* __restrict__ wk,
                         const float* __restrict__ wv, const float* __restrict__ wo,
                         const float* __restrict__ rel, const float* __restrict__ gbias,
                         const float* __restrict__ alphap, int total4) {
    int i = blockIdx.x * blockDim.x + threadIdx.x;
    if (i < total4) {
        float4 v = reinterpret_cast<const float4*>(x)[i];
        __half2 h0, h1;
        h0.x = __float2half(v.x); h0.y = __float2half(v.y);
        h1.x = __float2half(v.z); h1.y = __float2half(v.w);
        reinterpret_cast<__half2*>(g_xh)[i * 2]     = h0;
        reinterpret_cast<__half2*>(g_xh)[i * 2 + 1] = h1;
    }
    if (i < 768 * 768) {
        int o = i / 768, j = i % 768;
        int t = j >> 8, d = j & 255;
        const float* w = (o < 256) ? wq : (o < 512) ? wk : wv;
        int oc = o & 255;
        g_wh[i] = __float2half(w[(oc * 256 + d) * 3 + t]);
    }
    if (i < 256 * 256) {
        g_woh[i] = __float2half(wo[i]);
    }
    if (i < N_HEADS * 400) {
        int h = i / 400, rc = i % 400;
        int r = rc / 20, c = rc % 20;
        g_bias[i] = rel[(r - c + 19) * 8 + h] + alphap[0] * gbias[i];
    }
}

// ---------------- fused conv GEMM + LayerNorm + residual (R14-exact) ----------------
// Per block: 64 rows x 256 cols (one q/k/v segment). BK=64, 2-stage cp.async,
// single barrier per chunk, 2 CTAs/SM. Stage: A 8K | B 32K = 40K.
#define CSTAGE 40960
#define SMEM_CONV (2 * CSTAGE + 1024 + 2048)

__global__ __launch_bounds__(256, 2)
void conv_ln_kernel(const float* __restrict__ x,
                    const float* __restrict__ gq, const float* __restrict__ bq,
                    const float* __restrict__ gk, const float* __restrict__ bk,
                    const float* __restrict__ gv, const float* __restrict__ bv) {
    extern __shared__ __align__(16) char smem[];
    const uint32_t sb = smem_u32(smem);
    float* red = reinterpret_cast<float*>(smem + 2 * CSTAGE);          // [64][2]
    float* gam = reinterpret_cast<float*>(smem + 2 * CSTAGE + 1024);   // [256]
    float* bet = reinterpret_cast<float*>(smem + 2 * CSTAGE + 2048);   // [256]

    int tid = threadIdx.x, lane = tid & 31, wid = tid >> 5;
    int seg = blockIdx.x;              // 0=q 1=k 2=v
    int row0 = blockIdx.y * 64;
    int wm = (wid >> 2) * 32;          // 2 warp-rows of 32
    int wn = (wid & 3) * 64;           // 4 warp-cols of 64

    {
        const float* gsel = (seg == 0) ? gq : (seg == 1) ? gk : gv;
        const float* bsel = (seg == 0) ? bq : (seg == 1) ? bk : bv;
        gam[tid] = gsel[tid];
        bet[tid] = bsel[tid];
        if (tid < 128) red[tid] = 0.f;
    }

    float acc[2][8][4];
#pragma unroll
    for (int i = 0; i < 2; i++)
#pragma unroll
        for (int j = 0; j < 8; j++)
#pragma unroll
            for (int q = 0; q < 4; q++) acc[i][j][q] = 0.f;

    const uint32_t offA0 = swz128(wm + (lane & 15), (lane >> 4));
    const uint32_t offA1 = swz128(wm + 16 + (lane & 15), (lane >> 4));
    uint32_t offB[4];
#pragma unroll
    for (int np = 0; np < 4; np++)
        offB[np] = swz128(wn + np * 16 + (lane & 7) + ((lane >> 4) << 3),
                          (lane >> 3) & 1);

    auto issue = [&](int s, int kt) {
        uint32_t stg = sb + s * CSTAGE;
        int k0 = kt * 64;
        int t = kt >> 2;                 // tap (4 chunks of 64 per tap)
        int dbase = (kt & 3) * 64;
        // A: 64 rows x 64 fp16 = 8KB -> 512 cp16 = 2/thread
#pragma unroll
        for (int it = 0; it < 2; it++) {
            int f = it * 256 + tid;
            int r = f >> 3, kq = f & 7;
            int m = row0 + r;
            int n = m % N_NODES;
            int ns = n + t - 1;
            int ok = ((unsigned)ns < (unsigned)N_NODES);
            size_t src = (size_t)(ok ? (m + t - 1) : m) * 256 + dbase + kq * 8;
            int sz = ok ? 16 : 0;
            cp16(stg + swz128((uint32_t)r, (uint32_t)kq), g_xh + src, sz);
        }
        // B: 256 rows x 64 fp16 = 32KB -> 2048 cp16 = 8/thread
#pragma unroll
        for (int it = 0; it < 8; it++) {
            int f = it * 256 + tid;
            int r = f >> 3, kq = f & 7;
            size_t src = (size_t)(seg * 256 + r) * 768 + k0 + kq * 8;
            cp16(stg + 8192 + swz128((uint32_t)r, (uint32_t)kq), g_wh + src, 16);
        }
        cp_commit();
    };

    auto compute = [&](int s) {
        uint32_t base = sb + s * CSTAGE;
#pragma unroll
        for (int ks = 0; ks < 4; ks++) {
            uint32_t kx = (uint32_t)ks * 32;
            uint32_t fA[2][4];
            ldsm4(fA[0][0], fA[0][1], fA[0][2], fA[0][3], base + (offA0 ^ kx));
            ldsm4(fA[1][0], fA[1][1], fA[1][2], fA[1][3], base + (offA1 ^ kx));
#pragma unroll
            for (int np = 0; np < 4; np++) {
                uint32_t ad = base + 8192 + (offB[np] ^ kx);
                uint32_t b0, b1, b2, b3;
                ldsm4(b0, b1, b2, b3, ad);
#pragma unroll
                for (int mf = 0; mf < 2; mf++) {
                    mma_f16(acc[mf][2 * np],     fA[mf], b0, b1);
                    mma_f16(acc[mf][2 * np + 1], fA[mf], b2, b3);
                }
            }
        }
    };

    const int KT = 12;
    issue(0, 0);
#pragma unroll 1
    for (int kt = 0; kt < KT; kt++) {
        cp_wait<0>();
        __syncthreads();
        if (kt + 1 < KT) issue((kt + 1) & 1, kt + 1);
        compute(kt & 1);
    }

    // ---- LN + residual epilogue (fp16 output) ----
#pragma unroll
    for (int mf = 0; mf < 2; mf++) {
#pragma unroll
        for (int rr = 0; rr < 2; rr++) {
            int rloc = wm + mf * 16 + (lane >> 2) + rr * 8;
            float s = 0.f, s2 = 0.f;
#pragma unroll
            for (int nf = 0; nf < 8; nf++) {
                float c0 = acc[mf][nf][rr * 2];
                float c1 = acc[mf][nf][rr * 2 + 1];
                s += c0 + c1; s2 += c0 * c0 + c1 * c1;
            }
            s  += __shfl_xor_sync(0xffffffffu, s, 1);
            s  += __shfl_xor_sync(0xffffffffu, s, 2);
            s2 += __shfl_xor_sync(0xffffffffu, s2, 1);
            s2 += __shfl_xor_sync(0xffffffffu, s2, 2);
            if ((lane & 3) == 0) {
                atomicAdd(&red[rloc * 2], s);
                atomicAdd(&red[rloc * 2 + 1], s2);
            }
        }
    }
    __syncthreads();

#pragma unroll
    for (int mf = 0; mf < 2; mf++) {
#pragma unroll
        for (int rr = 0; rr < 2; rr++) {
            int rloc = wm + mf * 16 + (lane >> 2) + rr * 8;
            int rg = row0 + rloc;
            float mean = red[rloc * 2] * (1.0f / 256.0f);
            float var  = red[rloc * 2 + 1] * (1.0f / 256.0f) - mean * mean;
            float inv  = rsqrtf(var + 1e-5f);
#pragma unroll
            for (int nf = 0; nf < 8; nf++) {
                int cloc = wn + nf * 8 + 2 * (lane & 3);
                float2 xv = *reinterpret_cast<const float2*>(
                    &x[(size_t)rg * 256 + cloc]);
                float c0 = acc[mf][nf][rr * 2];
                float c1 = acc[mf][nf][rr * 2 + 1];
                float o0 = xv.x + (c0 - mean) * inv * gam[cloc]     + bet[cloc];
                float o1 = xv.y + (c1 - mean) * inv * gam[cloc + 1] + bet[cloc + 1];
                *reinterpret_cast<__half2*>(
                    &g_qkvh[(size_t)rg * 768 + seg * 256 + cloc]) =
                    __floats2half2_rn(o0, o1);
            }
        }
    }
}

// ---------------- proj GEMM (R14-exact: 64x256, BK=64, 2-stage) ----------------
#define SMEM_PROJ (2 * CSTAGE)

__global__ __launch_bounds__(256, 2)
void proj_gemm(const float* __restrict__ bo, float* __restrict__ outp) {
    extern __shared__ __align__(16) char smem[];
    const uint32_t sb = smem_u32(smem);

    int tid = threadIdx.x, lane = tid & 31, wid = tid >> 5;
    int row0 = blockIdx.x * 64;
    int wm = (wid >> 2) * 32;
    int wn = (wid & 3) * 64;

    float acc[2][8][4];
#pragma unroll
    for (int i = 0; i < 2; i++)
#pragma unroll
        for (int j = 0; j < 8; j++)
#pragma unroll
            for (int q = 0; q < 4; q++) acc[i][j][q] = 0.f;

    const uint32_t offA0 = swz128(wm + (lane & 15), (lane >> 4));
    const uint32_t offA1 = swz128(wm + 16 + (lane & 15), (lane >> 4));
    uint32_t offB[4];
#pragma unroll
    for (int np = 0; np < 4; np++)
        offB[np] = swz128(wn + np * 16 + (lane & 7) + ((lane >> 4) << 3),
                          (lane >> 3) & 1);

    auto issue = [&](int s, int kt) {
        uint32_t stg = sb + s * CSTAGE;
        int k0 = kt * 64;
#pragma unroll
        for (int it = 0; it < 2; it++) {
            int f = it * 256 + tid;
            int r = f >> 3, kq = f & 7;
            size_t src = (size_t)(row0 + r) * 256 + k0 + kq * 8;
            cp16(stg + swz128((uint32_t)r, (uint32_t)kq), g_ah + src, 16);
        }
#pragma unroll
        for (int it = 0; it < 8; it++) {
            int f = it * 256 + tid;
            int r = f >> 3, kq = f & 7;
            size_t src = (size_t)r * 256 + k0 + kq * 8;
            cp16(stg + 8192 + swz128((uint32_t)r, (uint32_t)kq), g_woh + src, 16);
        }
        cp_commit();
    };

    auto compute = [&](int s) {
        uint32_t base = sb + s * CSTAGE;
#pragma unroll
        for (int ks = 0; ks < 4; ks++) {
            uint32_t kx = (uint32_t)ks * 32;
            uint32_t fA[2][4];
            ldsm4(fA[0][0], fA[0][1], fA[0][2], fA[0][3], base + (offA0 ^ kx));
            ldsm4(fA[1][0], fA[1][1], fA[1][2], fA[1][3], base + (offA1 ^ kx));
#pragma unroll
            for (int np = 0; np < 4; np++) {
                uint32_t ad = base + 8192 + (offB[np] ^ kx);
                uint32_t b0, b1, b2, b3;
                ldsm4(b0, b1, b2, b3, ad);
#pragma unroll
                for (int mf = 0; mf < 2; mf++) {
                    mma_f16(acc[mf][2 * np],     fA[mf], b0, b1);
                    mma_f16(acc[mf][2 * np + 1], fA[mf], b2, b3);
                }
            }
        }
    };

    const int KT = 4;
    issue(0, 0);
#pragma unroll 1
    for (int kt = 0; kt < KT; kt++) {
        cp_wait<0>();
        __syncthreads();
        if (kt + 1 < KT) issue((kt + 1) & 1, kt + 1);
        compute(kt & 1);
    }

#pragma unroll
    for (int mf = 0; mf < 2; mf++) {
        int row = row0 + wm + mf * 16 + (lane >> 2);
#pragma unroll
        for (int nf = 0; nf < 8; nf++) {
            int col = wn + nf * 8 + 2 * (lane & 3);
            float* d = acc[mf][nf];
            float b0 = bo[col], b1 = bo[col + 1];
            *reinterpret_cast<float2*>(&outp[(size_t)row * 256 + col]) =
                make_float2(d[0] + b0, d[1] + b1);
            *reinterpret_cast<float2*>(&outp[(size_t)(row + 8) * 256 + col]) =
                make_float2(d[2] + b0, d[3] + b1);
        }
    }
}

// ---------------- attention: 8 warps = 8 heads per block, one block per batch ----------------
// smem: q 20480 | k 20480 | v 20480 | bias 12800 = 74240 bytes (dynamic)
#define SMEM_ATTN (3 * 20480 + 12800)

__global__ __launch_bounds__(256, 2)
void attn_kernel() {
    extern __shared__ __align__(16) char asmem[];
    int tid = threadIdx.x;
    int lane = tid & 31;
    int wid  = tid >> 5;          // = head h
    int h = wid;
    int b = blockIdx.x;

    __half* q_w = reinterpret_cast<__half*>(asmem + wid * 2560);
    __half* k_w = reinterpret_cast<__half*>(asmem + 20480 + wid * 2560);
    __half* v_w = reinterpret_cast<__half*>(asmem + 40960 + wid * 2560);
    float* bias_s = reinterpret_cast<float*>(asmem + 61440);

    // stage ALL heads' bias once per block (3200 floats = 800 float4)
    {
        const float4* src = reinterpret_cast<const float4*>(g_bias);
        float4* dst = reinterpret_cast<float4*>(bias_s);
        for (int i = tid; i < 800; i += 256) dst[i] = src[i];
    }

    // stage q,k,v rows for this warp's head (rows 0-19 data, 20-31 zero)
    {
        int r = lane;
        if (r < 20) {
            const __half* basep = &g_qkvh[(size_t)(b * 20 + r) * 768 + h * 32];
#pragma unroll
            for (int c = 0; c < 4; c++) {
                *reinterpret_cast<uint4*>(q_w + r * 40 + c * 8) =
                    *reinterpret_cast<const uint4*>(basep + c * 8);
                *reinterpret_cast<uint4*>(k_w + r * 40 + c * 8) =
                    *reinterpret_cast<const uint4*>(basep + 256 + c * 8);
                *reinterpret_cast<uint4*>(v_w + r * 40 + c * 8) =
                    *reinterpret_cast<const uint4*>(basep + 512 + c * 8);
            }
        } else {
            uint4 z = make_uint4(0, 0, 0, 0);
#pragma unroll
            for (int c = 0; c < 4; c++) {
                *reinterpret_cast<uint4*>(q_w + r * 40 + c * 8) = z;
                *reinterpret_cast<uint4*>(k_w + r * 40 + c * 8) = z;
                *reinterpret_cast<uint4*>(v_w + r * 40 + c * 8) = z;
            }
        }
    }
    __syncthreads();

    const uint32_t sq = smem_u32(q_w);
    const uint32_t sk = smem_u32(k_w);
    const uint32_t sv = smem_u32(v_w);
    int g = lane >> 2, t = lane & 3;
    const float* bias_h = bias_s + h * 400;

    // ---- QK^T ----
    float c[2][4][4];
#pragma unroll
    for (int i = 0; i < 2; i++)
#pragma unroll
        for (int j = 0; j < 4; j++)
#pragma unroll
            for (int q = 0; q < 4; q++) c[i][j][q] = 0.f;

#pragma unroll
    for (int ks = 0; ks < 2; ks++) {
        uint32_t a[2][4];
#pragma unroll
        for (int mt = 0; mt < 2; mt++) {
            uint32_t ad = sq + (mt * 16 + (lane & 15)) * 80 +
                          (ks * 16 + (lane >> 4) * 8) * 2;
            ldsm4(a[mt][0], a[mt][1], a[mt][2], a[mt][3], ad);
        }
        uint32_t bf[2][4];
#pragma unroll
        for (int np = 0; np < 2; np++) {
            uint32_t ad = sk + (np * 16 + (lane & 7) + ((lane >> 4) << 3)) * 80 +
                          (ks * 2 + ((lane >> 3) & 1)) * 16;
            ldsm4(bf[np][0], bf[np][1], bf[np][2], bf[np][3], ad);
        }
#pragma unroll
        for (int mt = 0; mt < 2; mt++)
#pragma unroll
            for (int nt = 0; nt < 4; nt++)
                mma_f16(c[mt][nt], a[mt],
                        bf[nt >> 1][(nt & 1) * 2], bf[nt >> 1][(nt & 1) * 2 + 1]);
    }

    // ---- bias + mask (smem table) ----
#pragma unroll
    for (int mt = 0; mt < 2; mt++)
#pragma unroll
        for (int nt = 0; nt < 4; nt++)
#pragma unroll
            for (int q = 0; q < 4; q++) {
                int row = mt * 16 + g + (q >> 1) * 8;
                int col = nt * 8 + 2 * t + (q & 1);
                if (row < 20 && col < 20) {
                    c[mt][nt][q] = c[mt][nt][q] * 0.17677669529663689f +
                                   bias_h[row * 20 + col];
                } else {
                    c[mt][nt][q] = -1e30f;
                }
            }

    // ---- softmax (quad shuffles) ----
#pragma unroll
    for (int mt = 0; mt < 2; mt++) {
        float m0 = -1e30f, m1 = -1e30f;
#pragma unroll
        for (int nt = 0; nt < 4; nt++) {
            m0 = fmaxf(m0, fmaxf(c[mt][nt][0], c[mt][nt][1]));
            m1 = fmaxf(m1, fmaxf(c[mt][nt][2], c[mt][nt][3]));
        }
        m0 = fmaxf(m0, __shfl_xor_sync(0xffffffffu, m0, 1));
        m0 = fmaxf(m0, __shfl_xor_sync(0xffffffffu, m0, 2));
        m1 = fmaxf(m1, __shfl_xor_sync(0xffffffffu, m1, 1));
        m1 = fmaxf(m1, __shfl_xor_sync(0xffffffffu, m1, 2));
        float s0 = 0.f, s1 = 0.f;
#pragma unroll
        for (int nt = 0; nt < 4; nt++) {
            c[mt][nt][0] = __expf(c[mt][nt][0] - m0);
            c[mt][nt][1] = __expf(c[mt][nt][1] - m0);
            c[mt][nt][2] = __expf(c[mt][nt][2] - m1);
            c[mt][nt][3] = __expf(c[mt][nt][3] - m1);
            s0 += c[mt][nt][0] + c[mt][nt][1];
            s1 += c[mt][nt][2] + c[mt][nt][3];
        }
        s0 += __shfl_xor_sync(0xffffffffu, s0, 1);
        s0 += __shfl_xor_sync(0xffffffffu, s0, 2);
        s1 += __shfl_xor_sync(0xffffffffu, s1, 1);
        s1 += __shfl_xor_sync(0xffffffffu, s1, 2);
        float i0 = 1.f / s0, i1 = 1.f / s1;
#pragma unroll
        for (int nt = 0; nt < 4; nt++) {
            c[mt][nt][0] *= i0; c[mt][nt][1] *= i0;
            c[mt][nt][2] *= i1; c[mt][nt][3] *= i1;
        }
    }

    // ---- AV ----
    float o[2][4][4];
#pragma unroll
    for (int i = 0; i < 2; i++)
#pragma unroll
        for (int j = 0; j < 4; j++)
#pragma unroll
            for (int q = 0; q < 4; q++) o[i][j][q] = 0.f;

#pragma unroll
    for (int ks = 0; ks < 2; ks++) {
        uint32_t pa[2][4];
#pragma unroll
        for (int mt = 0; mt < 2; mt++) {
            pa[mt][0] = pack_h2(c[mt][2 * ks][0],     c[mt][2 * ks][1]);
            pa[mt][1] = pack_h2(c[mt][2 * ks][2],     c[mt][2 * ks][3]);
            pa[mt][2] = pack_h2(c[mt][2 * ks + 1][0], c[mt][2 * ks + 1][1]);
            pa[mt][3] = pack_h2(c[mt][2 * ks + 1][2], c[mt][2 * ks + 1][3]);
        }
        uint32_t bv[2][4];
#pragma unroll
        for (int dp = 0; dp < 2; dp++) {
            uint32_t ad = sv + (ks * 16 + (lane & 15)) * 80 +
                          (dp * 16 + ((lane >> 4) << 3)) * 2;
            ldsm4t(bv[dp][0], bv[dp][1], bv[dp][2], bv[dp][3], ad);
        }
#pragma unroll
        for (int mt = 0; mt < 2; mt++)
#pragma unroll
            for (int nt = 0; nt < 4; nt++)
                mma_f16(o[mt][nt], pa[mt],
                        bv[nt >> 1][(nt & 1) * 2], bv[nt >> 1][(nt & 1) * 2 + 1]);
    }

    // ---- store rows < 20 ----
#pragma unroll
    for (int mt = 0; mt < 2; mt++)
#pragma unroll
        for (int q2 = 0; q2 < 2; q2++) {
            int row = mt * 16 + g + q2 * 8;
            if (row < 20) {
                __half* dst = &g_ah[(size_t)(b * 20 + row) * 256 + h * 32];
#pragma unroll
                for (int nt = 0; nt < 4; nt++) {
                    int col = nt * 8 + 2 * t;
                    *reinterpret_cast<__half2*>(dst + col) =
                        __floats2half2_rn(o[mt][nt][q2 * 2], o[mt][nt][q2 * 2 + 1]);
                }
            }
        }
}

// ---------------- launch ----------------
extern "C" void kernel_launch(void* const* d_in, const int* in_sizes, int n_in,
                              void* d_out, int out_size) {
    const float* x     = (const float*)d_in[0];
    const float* wq    = (const float*)d_in[1];
    const float* wk    = (const float*)d_in[2];
    const float* wv    = (const float*)d_in[3];
    const float* gq    = (const float*)d_in[4];
    const float* bq    = (const float*)d_in[5];
    const float* gk    = (const float*)d_in[6];
    const float* bk    = (const float*)d_in[7];
    const float* gv    = (const float*)d_in[8];
    const float* bv    = (const float*)d_in[9];
    const float* rel   = (const float*)d_in[10];
    const float* gbias = (const float*)d_in[11];
    const float* alpha = (const float*)d_in[12];
    const float* wo    = (const float*)d_in[13];
    const float* bo    = (const float*)d_in[14];
    float* out = (float*)d_out;

    int B = in_sizes[0] / (N_NODES * D_MODEL);
    int M = B * N_NODES;

    cudaFuncSetAttribute(conv_ln_kernel,
                         cudaFuncAttributeMaxDynamicSharedMemorySize, SMEM_CONV);
    cudaFuncSetAttribute(proj_gemm,
                         cudaFuncAttributeMaxDynamicSharedMemorySize, SMEM_PROJ);
    cudaFuncSetAttribute(attn_kernel,
                         cudaFuncAttributeMaxDynamicSharedMemorySize, SMEM_ATTN);

    int total4 = M * 64;
    prep_all<<<(total4 + 255) / 256, 256>>>(x, wq, wk, wv, wo, rel, gbias,
                                            alpha, total4);

    conv_ln_kernel<<<dim3(3, M / 64), 256, SMEM_CONV>>>(
        x, gq, bq, gk, bk, gv, bv);

    attn_kernel<<<B, 256, SMEM_ATTN>>>();

    proj_gemm<<<M / 64, 256, SMEM_PROJ>>>(bo, out);
}

// round 17
// speedup vs baseline: 1.0620x; 1.0228x over previous
#include <cuda_runtime.h>
#include <cuda_bf16.h>
#include <cuda_fp16.h>
#include <cstdint>

#define D_MODEL 256
#define N_NODES 20
#define N_HEADS 8
#define BMAX    8192
#define MMAX    (BMAX * N_NODES)   // 163840 rows

// ---------------- scratch (device globals: allocation-free) ----------------
__device__ __half g_xh[(size_t)MMAX * 256];     // x as fp16
__device__ __half g_wh[768 * 768];              // conv weights fp16 [o][j=t*256+i]
__device__ __half g_woh[256 * 256];             // wo fp16 [o][i]
__device__ __half g_qkvh[(size_t)MMAX * 768];   // q|k|v after LN+residual (fp16)
__device__ __half g_ah[(size_t)MMAX * 256];     // attn out fp16
__device__ float  g_bias[N_HEADS * 20 * 20];    // rel + alpha*gbias combined

// ---------------- warp-MMA helpers (baseline PTX: sm_80+) ----------------
__device__ __forceinline__ uint32_t smem_u32(const void* p) {
    uint32_t a;
    asm("{ .reg .u64 t; cvta.to.shared.u64 t, %1; cvt.u32.u64 %0, t; }"
        : "=r"(a) : "l"(p));
    return a;
}
__device__ __forceinline__ void ldsm4(uint32_t& r0, uint32_t& r1,
                                      uint32_t& r2, uint32_t& r3, uint32_t addr) {
    asm volatile("ldmatrix.sync.aligned.m8n8.x4.shared.b16 {%0,%1,%2,%3}, [%4];"
                 : "=r"(r0), "=r"(r1), "=r"(r2), "=r"(r3) : "r"(addr));
}
__device__ __forceinline__ void ldsm4t(uint32_t& r0, uint32_t& r1,
                                       uint32_t& r2, uint32_t& r3, uint32_t addr) {
    asm volatile("ldmatrix.sync.aligned.m8n8.x4.trans.shared.b16 {%0,%1,%2,%3}, [%4];"
                 : "=r"(r0), "=r"(r1), "=r"(r2), "=r"(r3) : "r"(addr));
}
__device__ __forceinline__ void mma_f16(float* d,
                                        const uint32_t* a,
                                        uint32_t b0, uint32_t b1) {
    asm volatile(
        "mma.sync.aligned.m16n8k16.row.col.f32.f16.f16.f32 "
        "{%0,%1,%2,%3}, {%4,%5,%6,%7}, {%8,%9}, {%0,%1,%2,%3};"
        : "+f"(d[0]), "+f"(d[1]), "+f"(d[2]), "+f"(d[3])
        : "r"(a[0]), "r"(a[1]), "r"(a[2]), "r"(a[3]), "r"(b0), "r"(b1));
}
__device__ __forceinline__ uint32_t pack_h2(float x, float y) {
    __half2 h = __floats2half2_rn(x, y);
    return *reinterpret_cast<uint32_t*>(&h);
}
__device__ __forceinline__ uint32_t swz128(uint32_t r, uint32_t kq) {
    return r * 128 + ((kq ^ (r & 7)) * 16);
}
__device__ __forceinline__ void cp16(uint32_t dst, const void* src, int srcsz) {
    asm volatile("cp.async.cg.shared.global [%0], [%1], 16, %2;"
                 :: "r"(dst), "l"(__cvta_generic_to_global(src)), "r"(srcsz)
                 : "memory");
}
__device__ __forceinline__ void cp_commit() {
    asm volatile("cp.async.commit_group;" ::: "memory");
}
template<int N>
__device__ __forceinline__ void cp_wait() {
    asm volatile("cp.async.wait_group %0;" :: "n"(N) : "memory");
}

// ---------------- merged prep kernel ----------------
__global__ void prep_all(const float* __restrict__ x,
                         const float* __restrict__ wq, const float* __restrict__ wk,
                         const float* __restrict__ wv, const float* __restrict__ wo,
                         const float* __restrict__ rel, const float* __restrict__ gbias,
                         const float* __restrict__ alphap, int total4) {
    int i = blockIdx.x * blockDim.x + threadIdx.x;
    if (i < total4) {
        float4 v = reinterpret_cast<const float4*>(x)[i];
        __half2 h0, h1;
        h0.x = __float2half(v.x); h0.y = __float2half(v.y);
        h1.x = __float2half(v.z); h1.y = __float2half(v.w);
        reinterpret_cast<__half2*>(g_xh)[i * 2]     = h0;
        reinterpret_cast<__half2*>(g_xh)[i * 2 + 1] = h1;
    }
    if (i < 768 * 768) {
        int o = i / 768, j = i % 768;
        int t = j >> 8, d = j & 255;
        const float* w = (o < 256) ? wq : (o < 512) ? wk : wv;
        int oc = o & 255;
        g_wh[i] = __float2half(w[(oc * 256 + d) * 3 + t]);
    }
    if (i < 256 * 256) {
        g_woh[i] = __float2half(wo[i]);
    }
    if (i < N_HEADS * 400) {
        int h = i / 400, rc = i % 400;
        int r = rc / 20, c = rc % 20;
        g_bias[i] = rel[(r - c + 19) * 8 + h] + alphap[0] * gbias[i];
    }
}

// ---------------- fused conv GEMM + LayerNorm + residual (R14-exact) ----------------
// Per block: 64 rows x 256 cols (one q/k/v segment). BK=64, 2-stage cp.async,
// single barrier per chunk, 2 CTAs/SM. Stage: A 8K | B 32K = 40K.
#define CSTAGE 40960
#define SMEM_CONV (2 * CSTAGE + 1024 + 2048)

__global__ __launch_bounds__(256, 2)
void conv_ln_kernel(const float* __restrict__ x,
                    const float* __restrict__ gq, const float* __restrict__ bq,
                    const float* __restrict__ gk, const float* __restrict__ bk,
                    const float* __restrict__ gv, const float* __restrict__ bv) {
    extern __shared__ __align__(16) char smem[];
    const uint32_t sb = smem_u32(smem);
    float* red = reinterpret_cast<float*>(smem + 2 * CSTAGE);          // [64][2]
    float* gam = reinterpret_cast<float*>(smem + 2 * CSTAGE + 1024);   // [256]
    float* bet = reinterpret_cast<float*>(smem + 2 * CSTAGE + 2048);   // [256]

    int tid = threadIdx.x, lane = tid & 31, wid = tid >> 5;
    int seg = blockIdx.x;              // 0=q 1=k 2=v
    int row0 = blockIdx.y * 64;
    int wm = (wid >> 2) * 32;          // 2 warp-rows of 32
    int wn = (wid & 3) * 64;           // 4 warp-cols of 64

    {
        const float* gsel = (seg == 0) ? gq : (seg == 1) ? gk : gv;
        const float* bsel = (seg == 0) ? bq : (seg == 1) ? bk : bv;
        gam[tid] = gsel[tid];
        bet[tid] = bsel[tid];
        if (tid < 128) red[tid] = 0.f;
    }

    float acc[2][8][4];
#pragma unroll
    for (int i = 0; i < 2; i++)
#pragma unroll
        for (int j = 0; j < 8; j++)
#pragma unroll
            for (int q = 0; q < 4; q++) acc[i][j][q] = 0.f;

    const uint32_t offA0 = swz128(wm + (lane & 15), (lane >> 4));
    const uint32_t offA1 = swz128(wm + 16 + (lane & 15), (lane >> 4));
    uint32_t offB[4];
#pragma unroll
    for (int np = 0; np < 4; np++)
        offB[np] = swz128(wn + np * 16 + (lane & 7) + ((lane >> 4) << 3),
                          (lane >> 3) & 1);

    auto issue = [&](int s, int kt) {
        uint32_t stg = sb + s * CSTAGE;
        int k0 = kt * 64;
        int t = kt >> 2;                 // tap (4 chunks of 64 per tap)
        int dbase = (kt & 3) * 64;
        // A: 64 rows x 64 fp16 = 8KB -> 512 cp16 = 2/thread
#pragma unroll
        for (int it = 0; it < 2; it++) {
            int f = it * 256 + tid;
            int r = f >> 3, kq = f & 7;
            int m = row0 + r;
            int n = m % N_NODES;
            int ns = n + t - 1;
            int ok = ((unsigned)ns < (unsigned)N_NODES);
            size_t src = (size_t)(ok ? (m + t - 1) : m) * 256 + dbase + kq * 8;
            int sz = ok ? 16 : 0;
            cp16(stg + swz128((uint32_t)r, (uint32_t)kq), g_xh + src, sz);
        }
        // B: 256 rows x 64 fp16 = 32KB -> 2048 cp16 = 8/thread
#pragma unroll
        for (int it = 0; it < 8; it++) {
            int f = it * 256 + tid;
            int r = f >> 3, kq = f & 7;
            size_t src = (size_t)(seg * 256 + r) * 768 + k0 + kq * 8;
            cp16(stg + 8192 + swz128((uint32_t)r, (uint32_t)kq), g_wh + src, 16);
        }
        cp_commit();
    };

    auto compute = [&](int s) {
        uint32_t base = sb + s * CSTAGE;
#pragma unroll
        for (int ks = 0; ks < 4; ks++) {
            uint32_t kx = (uint32_t)ks * 32;
            uint32_t fA[2][4];
            ldsm4(fA[0][0], fA[0][1], fA[0][2], fA[0][3], base + (offA0 ^ kx));
            ldsm4(fA[1][0], fA[1][1], fA[1][2], fA[1][3], base + (offA1 ^ kx));
#pragma unroll
            for (int np = 0; np < 4; np++) {
                uint32_t ad = base + 8192 + (offB[np] ^ kx);
                uint32_t b0, b1, b2, b3;
                ldsm4(b0, b1, b2, b3, ad);
#pragma unroll
                for (int mf = 0; mf < 2; mf++) {
                    mma_f16(acc[mf][2 * np],     fA[mf], b0, b1);
                    mma_f16(acc[mf][2 * np + 1], fA[mf], b2, b3);
                }
            }
        }
    };

    const int KT = 12;
    issue(0, 0);
#pragma unroll 1
    for (int kt = 0; kt < KT; kt++) {
        cp_wait<0>();
        __syncthreads();
        if (kt + 1 < KT) issue((kt + 1) & 1, kt + 1);
        compute(kt & 1);
    }

    // ---- LN + residual epilogue (fp16 output) ----
#pragma unroll
    for (int mf = 0; mf < 2; mf++) {
#pragma unroll
        for (int rr = 0; rr < 2; rr++) {
            int rloc = wm + mf * 16 + (lane >> 2) + rr * 8;
            float s = 0.f, s2 = 0.f;
#pragma unroll
            for (int nf = 0; nf < 8; nf++) {
                float c0 = acc[mf][nf][rr * 2];
                float c1 = acc[mf][nf][rr * 2 + 1];
                s += c0 + c1; s2 += c0 * c0 + c1 * c1;
            }
            s  += __shfl_xor_sync(0xffffffffu, s, 1);
            s  += __shfl_xor_sync(0xffffffffu, s, 2);
            s2 += __shfl_xor_sync(0xffffffffu, s2, 1);
            s2 += __shfl_xor_sync(0xffffffffu, s2, 2);
            if ((lane & 3) == 0) {
                atomicAdd(&red[rloc * 2], s);
                atomicAdd(&red[rloc * 2 + 1], s2);
            }
        }
    }
    __syncthreads();

#pragma unroll
    for (int mf = 0; mf < 2; mf++) {
#pragma unroll
        for (int rr = 0; rr < 2; rr++) {
            int rloc = wm + mf * 16 + (lane >> 2) + rr * 8;
            int rg = row0 + rloc;
            float mean = red[rloc * 2] * (1.0f / 256.0f);
            float var  = red[rloc * 2 + 1] * (1.0f / 256.0f) - mean * mean;
            float inv  = rsqrtf(var + 1e-5f);
#pragma unroll
            for (int nf = 0; nf < 8; nf++) {
                int cloc = wn + nf * 8 + 2 * (lane & 3);
                float2 xv = *reinterpret_cast<const float2*>(
                    &x[(size_t)rg * 256 + cloc]);
                float c0 = acc[mf][nf][rr * 2];
                float c1 = acc[mf][nf][rr * 2 + 1];
                float o0 = xv.x + (c0 - mean) * inv * gam[cloc]     + bet[cloc];
                float o1 = xv.y + (c1 - mean) * inv * gam[cloc + 1] + bet[cloc + 1];
                *reinterpret_cast<__half2*>(
                    &g_qkvh[(size_t)rg * 768 + seg * 256 + cloc]) =
                    __floats2half2_rn(o0, o1);
            }
        }
    }
}

// ---------------- proj GEMM (R14-exact: 64x256, BK=64, 2-stage) ----------------
#define SMEM_PROJ (2 * CSTAGE)

__global__ __launch_bounds__(256, 2)
void proj_gemm(const float* __restrict__ bo, float* __restrict__ outp) {
    extern __shared__ __align__(16) char smem[];
    const uint32_t sb = smem_u32(smem);

    int tid = threadIdx.x, lane = tid & 31, wid = tid >> 5;
    int row0 = blockIdx.x * 64;
    int wm = (wid >> 2) * 32;
    int wn = (wid & 3) * 64;

    float acc[2][8][4];
#pragma unroll
    for (int i = 0; i < 2; i++)
#pragma unroll
        for (int j = 0; j < 8; j++)
#pragma unroll
            for (int q = 0; q < 4; q++) acc[i][j][q] = 0.f;

    const uint32_t offA0 = swz128(wm + (lane & 15), (lane >> 4));
    const uint32_t offA1 = swz128(wm + 16 + (lane & 15), (lane >> 4));
    uint32_t offB[4];
#pragma unroll
    for (int np = 0; np < 4; np++)
        offB[np] = swz128(wn + np * 16 + (lane & 7) + ((lane >> 4) << 3),
                          (lane >> 3) & 1);

    auto issue = [&](int s, int kt) {
        uint32_t stg = sb + s * CSTAGE;
        int k0 = kt * 64;
#pragma unroll
        for (int it = 0; it < 2; it++) {
            int f = it * 256 + tid;
            int r = f >> 3, kq = f & 7;
            size_t src = (size_t)(row0 + r) * 256 + k0 + kq * 8;
            cp16(stg + swz128((uint32_t)r, (uint32_t)kq), g_ah + src, 16);
        }
#pragma unroll
        for (int it = 0; it < 8; it++) {
            int f = it * 256 + tid;
            int r = f >> 3, kq = f & 7;
            size_t src = (size_t)r * 256 + k0 + kq * 8;
            cp16(stg + 8192 + swz128((uint32_t)r, (uint32_t)kq), g_woh + src, 16);
        }
        cp_commit();
    };

    auto compute = [&](int s) {
        uint32_t base = sb + s * CSTAGE;
#pragma unroll
        for (int ks = 0; ks < 4; ks++) {
            uint32_t kx = (uint32_t)ks * 32;
            uint32_t fA[2][4];
            ldsm4(fA[0][0], fA[0][1], fA[0][2], fA[0][3], base + (offA0 ^ kx));
            ldsm4(fA[1][0], fA[1][1], fA[1][2], fA[1][3], base + (offA1 ^ kx));
#pragma unroll
            for (int np = 0; np < 4; np++) {
                uint32_t ad = base + 8192 + (offB[np] ^ kx);
                uint32_t b0, b1, b2, b3;
                ldsm4(b0, b1, b2, b3, ad);
#pragma unroll
                for (int mf = 0; mf < 2; mf++) {
                    mma_f16(acc[mf][2 * np],     fA[mf], b0, b1);
                    mma_f16(acc[mf][2 * np + 1], fA[mf], b2, b3);
                }
            }
        }
    };

    const int KT = 4;
    issue(0, 0);
#pragma unroll 1
    for (int kt = 0; kt < KT; kt++) {
        cp_wait<0>();
        __syncthreads();
        if (kt + 1 < KT) issue((kt + 1) & 1, kt + 1);
        compute(kt & 1);
    }

#pragma unroll
    for (int mf = 0; mf < 2; mf++) {
        int row = row0 + wm + mf * 16 + (lane >> 2);
#pragma unroll
        for (int nf = 0; nf < 8; nf++) {
            int col = wn + nf * 8 + 2 * (lane & 3);
            float* d = acc[mf][nf];
            float b0 = bo[col], b1 = bo[col + 1];
            *reinterpret_cast<float2*>(&outp[(size_t)row * 256 + col]) =
                make_float2(d[0] + b0, d[1] + b1);
            *reinterpret_cast<float2*>(&outp[(size_t)(row + 8) * 256 + col]) =
                make_float2(d[2] + b0, d[3] + b1);
        }
    }
}

// ---------------- attention (R14-exact): HMMA per (b, head), smem bias ----------------
__global__ __launch_bounds__(128)
void attn_kernel() {
    __shared__ __half q_s[4][32][40];
    __shared__ __half k_s[4][32][40];
    __shared__ __half v_s[4][32][40];
    __shared__ float bias_s[4][400];
    int lane = threadIdx.x & 31;
    int wid  = threadIdx.x >> 5;
    int h = blockIdx.y * 4 + wid;
    int b = blockIdx.x;
    int tid = threadIdx.x;

    {
        const float* src = &g_bias[blockIdx.y * 4 * 400];
        float* dst = &bias_s[0][0];
        for (int i = tid; i < 400; i += 128)
            *reinterpret_cast<float4*>(dst + i * 4) =
                *reinterpret_cast<const float4*>(src + i * 4);
    }

    {
        int r = lane;
        if (r < 20) {
            const __half* basep = &g_qkvh[(size_t)(b * 20 + r) * 768 + h * 32];
#pragma unroll
            for (int c = 0; c < 4; c++) {
                *reinterpret_cast<uint4*>(&q_s[wid][r][c * 8]) =
                    *reinterpret_cast<const uint4*>(basep + c * 8);
                *reinterpret_cast<uint4*>(&k_s[wid][r][c * 8]) =
                    *reinterpret_cast<const uint4*>(basep + 256 + c * 8);
                *reinterpret_cast<uint4*>(&v_s[wid][r][c * 8]) =
                    *reinterpret_cast<const uint4*>(basep + 512 + c * 8);
            }
        } else {
            uint4 z = make_uint4(0, 0, 0, 0);
#pragma unroll
            for (int c = 0; c < 4; c++) {
                *reinterpret_cast<uint4*>(&q_s[wid][r][c * 8]) = z;
                *reinterpret_cast<uint4*>(&k_s[wid][r][c * 8]) = z;
                *reinterpret_cast<uint4*>(&v_s[wid][r][c * 8]) = z;
            }
        }
    }
    __syncthreads();

    const uint32_t sq = smem_u32(&q_s[wid][0][0]);
    const uint32_t sk = smem_u32(&k_s[wid][0][0]);
    const uint32_t sv = smem_u32(&v_s[wid][0][0]);
    int g = lane >> 2, t = lane & 3;

    float c[2][4][4];
#pragma unroll
    for (int i = 0; i < 2; i++)
#pragma unroll
        for (int j = 0; j < 4; j++)
#pragma unroll
            for (int q = 0; q < 4; q++) c[i][j][q] = 0.f;

#pragma unroll
    for (int ks = 0; ks < 2; ks++) {
        uint32_t a[2][4];
#pragma unroll
        for (int mt = 0; mt < 2; mt++) {
            uint32_t ad = sq + (mt * 16 + (lane & 15)) * 80 +
                          (ks * 16 + (lane >> 4) * 8) * 2;
            ldsm4(a[mt][0], a[mt][1], a[mt][2], a[mt][3], ad);
        }
        uint32_t bf[2][4];
#pragma unroll
        for (int np = 0; np < 2; np++) {
            uint32_t ad = sk + (np * 16 + (lane & 7) + ((lane >> 4) << 3)) * 80 +
                          (ks * 2 + ((lane >> 3) & 1)) * 16;
            ldsm4(bf[np][0], bf[np][1], bf[np][2], bf[np][3], ad);
        }
#pragma unroll
        for (int mt = 0; mt < 2; mt++)
#pragma unroll
            for (int nt = 0; nt < 4; nt++)
                mma_f16(c[mt][nt], a[mt],
                        bf[nt >> 1][(nt & 1) * 2], bf[nt >> 1][(nt & 1) * 2 + 1]);
    }

#pragma unroll
    for (int mt = 0; mt < 2; mt++)
#pragma unroll
        for (int nt = 0; nt < 4; nt++)
#pragma unroll
            for (int q = 0; q < 4; q++) {
                int row = mt * 16 + g + (q >> 1) * 8;
                int col = nt * 8 + 2 * t + (q & 1);
                if (row < 20 && col < 20) {
                    c[mt][nt][q] = c[mt][nt][q] * 0.17677669529663689f +
                                   bias_s[wid][row * 20 + col];
                } else {
                    c[mt][nt][q] = -1e30f;
                }
            }

#pragma unroll
    for (int mt = 0; mt < 2; mt++) {
        float m0 = -1e30f, m1 = -1e30f;
#pragma unroll
        for (int nt = 0; nt < 4; nt++) {
            m0 = fmaxf(m0, fmaxf(c[mt][nt][0], c[mt][nt][1]));
            m1 = fmaxf(m1, fmaxf(c[mt][nt][2], c[mt][nt][3]));
        }
        m0 = fmaxf(m0, __shfl_xor_sync(0xffffffffu, m0, 1));
        m0 = fmaxf(m0, __shfl_xor_sync(0xffffffffu, m0, 2));
        m1 = fmaxf(m1, __shfl_xor_sync(0xffffffffu, m1, 1));
        m1 = fmaxf(m1, __shfl_xor_sync(0xffffffffu, m1, 2));
        float s0 = 0.f, s1 = 0.f;
#pragma unroll
        for (int nt = 0; nt < 4; nt++) {
            c[mt][nt][0] = __expf(c[mt][nt][0] - m0);
            c[mt][nt][1] = __expf(c[mt][nt][1] - m0);
            c[mt][nt][2] = __expf(c[mt][nt][2] - m1);
            c[mt][nt][3] = __expf(c[mt][nt][3] - m1);
            s0 += c[mt][nt][0] + c[mt][nt][1];
            s1 += c[mt][nt][2] + c[mt][nt][3];
        }
        s0 += __shfl_xor_sync(0xffffffffu, s0, 1);
        s0 += __shfl_xor_sync(0xffffffffu, s0, 2);
        s1 += __shfl_xor_sync(0xffffffffu, s1, 1);
        s1 += __shfl_xor_sync(0xffffffffu, s1, 2);
        float i0 = 1.f / s0, i1 = 1.f / s1;
#pragma unroll
        for (int nt = 0; nt < 4; nt++) {
            c[mt][nt][0] *= i0; c[mt][nt][1] *= i0;
            c[mt][nt][2] *= i1; c[mt][nt][3] *= i1;
        }
    }

    float o[2][4][4];
#pragma unroll
    for (int i = 0; i < 2; i++)
#pragma unroll
        for (int j = 0; j < 4; j++)
#pragma unroll
            for (int q = 0; q < 4; q++) o[i][j][q] = 0.f;

#pragma unroll
    for (int ks = 0; ks < 2; ks++) {
        uint32_t pa[2][4];
#pragma unroll
        for (int mt = 0; mt < 2; mt++) {
            pa[mt][0] = pack_h2(c[mt][2 * ks][0],     c[mt][2 * ks][1]);
            pa[mt][1] = pack_h2(c[mt][2 * ks][2],     c[mt][2 * ks][3]);
            pa[mt][2] = pack_h2(c[mt][2 * ks + 1][0], c[mt][2 * ks + 1][1]);
            pa[mt][3] = pack_h2(c[mt][2 * ks + 1][2], c[mt][2 * ks + 1][3]);
        }
        uint32_t bv[2][4];
#pragma unroll
        for (int dp = 0; dp < 2; dp++) {
            uint32_t ad = sv + (ks * 16 + (lane & 15)) * 80 +
                          (dp * 16 + ((lane >> 4) << 3)) * 2;
            ldsm4t(bv[dp][0], bv[dp][1], bv[dp][2], bv[dp][3], ad);
        }
#pragma unroll
        for (int mt = 0; mt < 2; mt++)
#pragma unroll
            for (int nt = 0; nt < 4; nt++)
                mma_f16(o[mt][nt], pa[mt],
                        bv[nt >> 1][(nt & 1) * 2], bv[nt >> 1][(nt & 1) * 2 + 1]);
    }

#pragma unroll
    for (int mt = 0; mt < 2; mt++)
#pragma unroll
        for (int q2 = 0; q2 < 2; q2++) {
            int row = mt * 16 + g + q2 * 8;
            if (row < 20) {
                __half* dst = &g_ah[(size_t)(b * 20 + row) * 256 + h * 32];
#pragma unroll
                for (int nt = 0; nt < 4; nt++) {
                    int col = nt * 8 + 2 * t;
                    *reinterpret_cast<__half2*>(dst + col) =
                        __floats2half2_rn(o[mt][nt][q2 * 2], o[mt][nt][q2 * 2 + 1]);
                }
            }
        }
}

// ---------------- launch ----------------
extern "C" void kernel_launch(void* const* d_in, const int* in_sizes, int n_in,
                              void* d_out, int out_size) {
    const float* x     = (const float*)d_in[0];
    const float* wq    = (const float*)d_in[1];
    const float* wk    = (const float*)d_in[2];
    const float* wv    = (const float*)d_in[3];
    const float* gq    = (const float*)d_in[4];
    const float* bq    = (const float*)d_in[5];
    const float* gk    = (const float*)d_in[6];
    const float* bk    = (const float*)d_in[7];
    const float* gv    = (const float*)d_in[8];
    const float* bv    = (const float*)d_in[9];
    const float* rel   = (const float*)d_in[10];
    const float* gbias = (const float*)d_in[11];
    const float* alpha = (const float*)d_in[12];
    const float* wo    = (const float*)d_in[13];
    const float* bo    = (const float*)d_in[14];
    float* out = (float*)d_out;

    int B = in_sizes[0] / (N_NODES * D_MODEL);
    int M = B * N_NODES;

    cudaFuncSetAttribute(conv_ln_kernel,
                         cudaFuncAttributeMaxDynamicSharedMemorySize, SMEM_CONV);
    cudaFuncSetAttribute(proj_gemm,
                         cudaFuncAttributeMaxDynamicSharedMemorySize, SMEM_PROJ);

    int total4 = M * 64;
    prep_all<<<(total4 + 255) / 256, 256>>>(x, wq, wk, wv, wo, rel, gbias,
                                            alpha, total4);

    conv_ln_kernel<<<dim3(3, M / 64), 256, SMEM_CONV>>>(
        x, gq, bq, gk, bk, gv, bv);

    attn_kernel<<<dim3(B, 2), 128>>>();

    proj_gemm<<<M / 64, 256, SMEM_PROJ>>>(bo, out);
}